// round 6
// baseline (speedup 1.0000x reference)
#include <cuda_runtime.h>
#include <math.h>

#define N_NODES_MAX 50000
#define HDIM 64
#define N_GRAPHS 64

// Scratch (device globals — allocation-free). Referenced directly in device
// code so kernel_launch is pure kernel launches (graph-capture safe).
__device__ __align__(16) float g_h[N_NODES_MAX * HDIM];     // 12.8 MB
__device__ __align__(16) float g_agg[N_NODES_MAX * HDIM];   // 12.8 MB
__device__ __align__(16) float g_gsum[N_GRAPHS * HDIM];
__device__ __align__(16) float g_gcnt[N_GRAPHS];

// ---------------------------------------------------------------------------
// Zero g_agg (grid-stride float4)
// ---------------------------------------------------------------------------
__global__ void zero_agg_kernel(int n4) {
    int i = blockIdx.x * blockDim.x + threadIdx.x;
    float4 z = {0.f, 0.f, 0.f, 0.f};
    for (; i < n4; i += gridDim.x * blockDim.x)
        ((float4*)g_agg)[i] = z;
}

// Zero pool accumulators (tiny)
__global__ void zero_pool_kernel() {
    int i = blockIdx.x * blockDim.x + threadIdx.x;
    if (i < N_GRAPHS * HDIM) g_gsum[i] = 0.f;
    if (i < N_GRAPHS)        g_gcnt[i] = 0.f;
}

// ---------------------------------------------------------------------------
// Node-feature GEMM:  g_h[n, 64] = f(src_row(n)) @ W[K, 64]
//   SRC_AGG ? source = g_agg : source = X
//   f(v) = PRE ? relu(v + preb[k]) : v
// Block: 256 threads = 16 col-groups (float4) x 16 rows.
// ---------------------------------------------------------------------------
template <int K, bool PRE, bool SRC_AGG>
__global__ void gemm_nodes(const float* __restrict__ X,
                           const float* __restrict__ Wg,
                           const float* __restrict__ preb,
                           int N) {
    __shared__ float  xs[16 * (K + 4)];
    __shared__ float4 ws[K * 16];

    int tid = threadIdx.x;

    for (int i = tid; i < K * 16; i += 256)
        ws[i] = ((const float4*)Wg)[i];

    int row0 = blockIdx.x * 16;

    for (int i = tid; i < 16 * K; i += 256) {
        int r = i / K, k = i - r * K;
        int row = row0 + r;
        float v = 0.f;
        if (row < N) {
            v = SRC_AGG ? g_agg[row * K + k] : X[row * K + k];
            if (PRE) v = fmaxf(v + preb[k], 0.f);
        }
        xs[r * (K + 4) + k] = v;
    }
    __syncthreads();

    int cg = tid & 15;
    int r  = tid >> 4;

    float4 acc = {0.f, 0.f, 0.f, 0.f};
    const float* xrow = &xs[r * (K + 4)];
#pragma unroll
    for (int k = 0; k < K; ++k) {
        float  xv = xrow[k];
        float4 w  = ws[k * 16 + cg];
        acc.x += xv * w.x;
        acc.y += xv * w.y;
        acc.z += xv * w.z;
        acc.w += xv * w.w;
    }

    int row = row0 + r;
    if (row < N)
        ((float4*)&g_h[row * HDIM])[cg] = acc;
}

// ---------------------------------------------------------------------------
// Edge scatter-add: g_agg[dst] += g_h[src].
// 16 lanes per edge; each lane does one coalesced float4 load + one
// vector float4 atomicAdd (sm_90+).  edge_index is INT32 (JAX x64 disabled).
// ---------------------------------------------------------------------------
__global__ void scatter_kernel(const int* __restrict__ ei, int E) {
    int t = blockIdx.x * blockDim.x + threadIdx.x;
    int e = t >> 4;
    if (e >= E) return;
    int lane = t & 15;
    int src = __ldg(&ei[e]);
    int dst = __ldg(&ei[E + e]);
    float4 v = *(const float4*)(g_h + src * HDIM + lane * 4);
    atomicAdd((float4*)(g_agg + dst * HDIM + lane * 4), v);
}

// ---------------------------------------------------------------------------
// Mean-pool stage 1: per-graph sums of relu(g_agg + b2) and node counts.
// 16 lanes per node, float4 vector atomics.  batch is INT32.
// ---------------------------------------------------------------------------
__global__ void pool_kernel(const float* __restrict__ b2,
                            const int* __restrict__ batch, int N) {
    int t = blockIdx.x * blockDim.x + threadIdx.x;
    int n = t >> 4;
    if (n >= N) return;
    int lane = t & 15;
    int g = __ldg(&batch[n]);
    float4 a = *(const float4*)(g_agg + n * HDIM + lane * 4);
    float4 bb = *(const float4*)(b2 + lane * 4);
    float4 v;
    v.x = fmaxf(a.x + bb.x, 0.f);
    v.y = fmaxf(a.y + bb.y, 0.f);
    v.z = fmaxf(a.z + bb.z, 0.f);
    v.w = fmaxf(a.w + bb.w, 0.f);
    atomicAdd((float4*)(g_gsum + g * HDIM + lane * 4), v);
    if (lane == 0) atomicAdd(&g_gcnt[g], 1.0f);
}

// ---------------------------------------------------------------------------
// Head: pooled -> fc1(relu) -> fc2 -> log_softmax.  One thread per graph.
// ---------------------------------------------------------------------------
__global__ void head_kernel(const float* __restrict__ fc1w,  // [64,32]
                            const float* __restrict__ fc1b,
                            const float* __restrict__ fc2w,  // [32,10]
                            const float* __restrict__ fc2b,
                            float* __restrict__ out) {
    int g = threadIdx.x;
    if (g >= N_GRAPHS) return;

    float inv = 1.0f / fmaxf(g_gcnt[g], 1.0f);
    float p[HDIM];
#pragma unroll
    for (int c = 0; c < HDIM; ++c) p[c] = g_gsum[g * HDIM + c] * inv;

    float z1[32];
#pragma unroll
    for (int j = 0; j < 32; ++j) {
        float s = fc1b[j];
#pragma unroll
        for (int c = 0; c < HDIM; ++c) s += p[c] * fc1w[c * 32 + j];
        z1[j] = fmaxf(s, 0.f);
    }

    float z2[10];
    float m = -1e30f;
#pragma unroll
    for (int k = 0; k < 10; ++k) {
        float s = fc2b[k];
#pragma unroll
        for (int j = 0; j < 32; ++j) s += z1[j] * fc2w[j * 10 + k];
        z2[k] = s;
        m = fmaxf(m, s);
    }
    float se = 0.f;
#pragma unroll
    for (int k = 0; k < 10; ++k) se += expf(z2[k] - m);
    float lse = m + logf(se);
#pragma unroll
    for (int k = 0; k < 10; ++k) out[g * 10 + k] = z2[k] - lse;
}

// ---------------------------------------------------------------------------
// Launch — kernel launches ONLY
// ---------------------------------------------------------------------------
extern "C" void kernel_launch(void* const* d_in, const int* in_sizes, int n_in,
                              void* d_out, int out_size) {
    const float* x     = (const float*)d_in[0];
    const int*   ei    = (const int*)d_in[1];    // int32 (JAX x64 disabled)
    const int*   batch = (const int*)d_in[2];    // int32
    const float* W1    = (const float*)d_in[3];
    const float* b1    = (const float*)d_in[4];
    const float* W2    = (const float*)d_in[5];
    const float* b2    = (const float*)d_in[6];
    const float* fc1w  = (const float*)d_in[7];
    const float* fc1b  = (const float*)d_in[8];
    const float* fc2w  = (const float*)d_in[9];
    const float* fc2b  = (const float*)d_in[10];
    float* out = (float*)d_out;

    int N = in_sizes[0] / 128;   // nodes
    int E = in_sizes[1] / 2;     // edges

    int gemm_blocks    = (N + 15) / 16;
    int scatter_blocks = (E * 16 + 255) / 256;
    int pool_blocks    = (N * 16 + 255) / 256;
    int agg4           = N * HDIM / 4;

    // 1. g_h = x @ W1
    gemm_nodes<128, false, false><<<gemm_blocks, 256>>>(x, W1, b1, N);
    // 2. zero g_agg + pool accumulators
    zero_agg_kernel<<<512, 256>>>(agg4);
    zero_pool_kernel<<<(N_GRAPHS * HDIM + 255) / 256, 256>>>();
    // 3. g_agg += g_h[src]
    scatter_kernel<<<scatter_blocks, 256>>>(ei, E);
    // 4. g_h = relu(g_agg + b1) @ W2
    gemm_nodes<64, true, true><<<gemm_blocks, 256>>>(x, W2, b1, N);
    // 5. zero g_agg
    zero_agg_kernel<<<512, 256>>>(agg4);
    // 6. g_agg += g_h[src]
    scatter_kernel<<<scatter_blocks, 256>>>(ei, E);
    // 7. per-graph sums of relu(g_agg + b2) + counts
    pool_kernel<<<pool_blocks, 256>>>(b2, batch, N);
    // 8. MLP head + log_softmax
    head_kernel<<<1, 64>>>(fc1w, fc1b, fc2w, fc2b, out);
}

// round 7
// speedup vs baseline: 1.1996x; 1.1996x over previous
#include <cuda_runtime.h>
#include <math.h>

#define N_NODES_MAX 50000
#define N_EDGES_MAX 800000
#define HDIM 64
#define N_GRAPHS 64

// Scratch (device globals — allocation-free, referenced directly in kernels)
__device__ __align__(16) float g_h[N_NODES_MAX * HDIM];     // 12.8 MB
__device__ __align__(16) float g_agg[N_NODES_MAX * HDIM];   // 12.8 MB
__device__ __align__(16) float g_gsum[N_GRAPHS * HDIM];
__device__ __align__(16) float g_gcnt[N_GRAPHS];
__device__ int g_deg[N_NODES_MAX + 1];
__device__ int g_rowptr[N_NODES_MAX + 1];
__device__ int g_cursor[N_NODES_MAX + 1];
__device__ int g_col[N_EDGES_MAX];

// ---------------------------------------------------------------------------
// Zero degree histogram + pool accumulators
// ---------------------------------------------------------------------------
__global__ void zero_small_kernel(int N) {
    int i = blockIdx.x * blockDim.x + threadIdx.x;
    if (i <= N)               g_deg[i]  = 0;
    if (i < N_GRAPHS * HDIM)  g_gsum[i] = 0.f;
    if (i < N_GRAPHS)         g_gcnt[i] = 0.f;
}

// ---------------------------------------------------------------------------
// CSR build: histogram over dst, exclusive scan, fill column list
// ---------------------------------------------------------------------------
__global__ void hist_kernel(const int* __restrict__ ei, int E) {
    int e = blockIdx.x * blockDim.x + threadIdx.x;
    if (e < E) atomicAdd(&g_deg[__ldg(&ei[E + e])], 1);
}

// Single-block exclusive scan of g_deg[0..N) -> g_rowptr / g_cursor
__global__ void scan_kernel(int N) {
    __shared__ int wsum[32];
    __shared__ int s_carry;
    int tid = threadIdx.x, lane = tid & 31, wid = tid >> 5;
    if (tid == 0) s_carry = 0;
    __syncthreads();
    for (int base = 0; base < N; base += 1024) {
        int idx = base + tid;
        int v = (idx < N) ? g_deg[idx] : 0;
        int x = v;
#pragma unroll
        for (int o = 1; o < 32; o <<= 1) {
            int y = __shfl_up_sync(0xffffffffu, x, o);
            if (lane >= o) x += y;
        }
        if (lane == 31) wsum[wid] = x;
        __syncthreads();
        if (wid == 0) {
            int t = wsum[lane];
#pragma unroll
            for (int o = 1; o < 32; o <<= 1) {
                int y = __shfl_up_sync(0xffffffffu, t, o);
                if (lane >= o) t += y;
            }
            wsum[lane] = t;
        }
        __syncthreads();
        int incl = x + (wid > 0 ? wsum[wid - 1] : 0);
        int excl = incl - v + s_carry;
        if (idx < N) { g_rowptr[idx] = excl; g_cursor[idx] = excl; }
        int total = wsum[31];
        __syncthreads();
        if (tid == 0) s_carry += total;
        __syncthreads();
    }
    if (threadIdx.x == 0) g_rowptr[N] = s_carry;
}

__global__ void fill_kernel(const int* __restrict__ ei, int E) {
    int e = blockIdx.x * blockDim.x + threadIdx.x;
    if (e >= E) return;
    int src = __ldg(&ei[e]);
    int dst = __ldg(&ei[E + e]);
    int p = atomicAdd(&g_cursor[dst], 1);
    g_col[p] = src;
}

// ---------------------------------------------------------------------------
// Atomic-free gather: one warp per node, each lane owns 2 feature columns.
//   MODE 0: g_agg[n] = sum_{src in-edges} g_h[src]
//   MODE 1: v = relu(sum + b2); red into g_gsum[batch[n]], count into g_gcnt
// ---------------------------------------------------------------------------
template <int MODE>
__global__ void gather_kernel(const float* __restrict__ b2,
                              const int* __restrict__ batch, int N) {
    int w = (blockIdx.x * blockDim.x + threadIdx.x) >> 5;
    if (w >= N) return;
    int lane = threadIdx.x & 31;
    int beg = __ldg(&g_rowptr[w]);
    int end = __ldg(&g_rowptr[w + 1]);

    const float2* hp = (const float2*)g_h;
    float2 acc = {0.f, 0.f};

    int i = beg;
    while (i < end) {
        int m = min(32, end - i);
        int c = (lane < m) ? __ldg(&g_col[i + lane]) : 0;
        int j = 0;
        for (; j + 4 <= m; j += 4) {
            int s0 = __shfl_sync(0xffffffffu, c, j);
            int s1 = __shfl_sync(0xffffffffu, c, j + 1);
            int s2 = __shfl_sync(0xffffffffu, c, j + 2);
            int s3 = __shfl_sync(0xffffffffu, c, j + 3);
            float2 v0 = hp[s0 * 32 + lane];
            float2 v1 = hp[s1 * 32 + lane];
            float2 v2 = hp[s2 * 32 + lane];
            float2 v3 = hp[s3 * 32 + lane];
            acc.x += v0.x + v1.x + v2.x + v3.x;
            acc.y += v0.y + v1.y + v2.y + v3.y;
        }
        for (; j < m; ++j) {
            int s = __shfl_sync(0xffffffffu, c, j);
            float2 v = hp[s * 32 + lane];
            acc.x += v.x;
            acc.y += v.y;
        }
        i += m;
    }

    if (MODE == 0) {
        ((float2*)g_agg)[w * 32 + lane] = acc;
    } else {
        float bx = __ldg(&b2[lane * 2]);
        float by = __ldg(&b2[lane * 2 + 1]);
        float vx = fmaxf(acc.x + bx, 0.f);
        float vy = fmaxf(acc.y + by, 0.f);
        int g = __ldg(&batch[w]);
        atomicAdd(&g_gsum[g * HDIM + lane * 2],     vx);
        atomicAdd(&g_gsum[g * HDIM + lane * 2 + 1], vy);
        if (lane == 0) atomicAdd(&g_gcnt[g], 1.0f);
    }
}

// ---------------------------------------------------------------------------
// Register-tiled GEMM: g_h[n,64] = f(src(n,:K)) @ W[K,64]
// Block = 256 threads, tile 128 rows x 64 cols; thread computes 8 rows x 4 cols.
// K staged in 32-wide chunks. f = PRE ? relu(v + preb) : v; SRC_AGG ? g_agg : X.
// ---------------------------------------------------------------------------
template <int K, bool PRE, bool SRC_AGG>
__global__ void gemm_nodes(const float* __restrict__ X,
                           const float* __restrict__ Wg,
                           const float* __restrict__ preb,
                           int N) {
    const int KC = 32;
    __shared__ float  xs[128][KC + 1];
    __shared__ float4 ws[KC][16];

    int tid = threadIdx.x;
    int cg  = tid & 15;   // column group (4 cols)
    int rt  = tid >> 4;   // row-thread (8 rows)
    int row0 = blockIdx.x * 128;

    float4 acc[8];
#pragma unroll
    for (int i = 0; i < 8; ++i) acc[i] = make_float4(0.f, 0.f, 0.f, 0.f);

    for (int kc = 0; kc < K; kc += KC) {
        // Stage W chunk: 32 x 16 float4
#pragma unroll
        for (int j = 0; j < 2; ++j) {
            int id = tid + 256 * j;
            int k = id >> 4, c = id & 15;
            ws[k][c] = ((const float4*)Wg)[(kc + k) * 16 + c];
        }
        // Stage X chunk: 128 rows x 32 cols
#pragma unroll
        for (int j = 0; j < 4; ++j) {
            int q = tid + 256 * j;
            int r = q >> 3, c4 = q & 7;
            int row = row0 + r;
            float4 v = make_float4(0.f, 0.f, 0.f, 0.f);
            if (row < N) {
                const float* srcp = SRC_AGG ? g_agg : X;
                v = *(const float4*)(srcp + row * K + kc + c4 * 4);
                if (PRE) {
                    int kb = kc + c4 * 4;
                    v.x = fmaxf(v.x + __ldg(&preb[kb]),     0.f);
                    v.y = fmaxf(v.y + __ldg(&preb[kb + 1]), 0.f);
                    v.z = fmaxf(v.z + __ldg(&preb[kb + 2]), 0.f);
                    v.w = fmaxf(v.w + __ldg(&preb[kb + 3]), 0.f);
                }
            }
            xs[r][c4 * 4]     = v.x;
            xs[r][c4 * 4 + 1] = v.y;
            xs[r][c4 * 4 + 2] = v.z;
            xs[r][c4 * 4 + 3] = v.w;
        }
        __syncthreads();

#pragma unroll
        for (int kk = 0; kk < KC; ++kk) {
            float4 w = ws[kk][cg];
#pragma unroll
            for (int i = 0; i < 8; ++i) {
                float xv = xs[rt * 8 + i][kk];
                acc[i].x += xv * w.x;
                acc[i].y += xv * w.y;
                acc[i].z += xv * w.z;
                acc[i].w += xv * w.w;
            }
        }
        __syncthreads();
    }

#pragma unroll
    for (int i = 0; i < 8; ++i) {
        int row = row0 + rt * 8 + i;
        if (row < N)
            ((float4*)&g_h[row * HDIM])[cg] = acc[i];
    }
}

// ---------------------------------------------------------------------------
// Head: pooled -> fc1(relu) -> fc2 -> log_softmax. One thread per graph.
// ---------------------------------------------------------------------------
__global__ void head_kernel(const float* __restrict__ fc1w,  // [64,32]
                            const float* __restrict__ fc1b,
                            const float* __restrict__ fc2w,  // [32,10]
                            const float* __restrict__ fc2b,
                            float* __restrict__ out) {
    int g = threadIdx.x;
    if (g >= N_GRAPHS) return;

    float inv = 1.0f / fmaxf(g_gcnt[g], 1.0f);
    float p[HDIM];
#pragma unroll
    for (int c = 0; c < HDIM; ++c) p[c] = g_gsum[g * HDIM + c] * inv;

    float z1[32];
#pragma unroll
    for (int j = 0; j < 32; ++j) {
        float s = fc1b[j];
#pragma unroll
        for (int c = 0; c < HDIM; ++c) s += p[c] * fc1w[c * 32 + j];
        z1[j] = fmaxf(s, 0.f);
    }

    float z2[10];
    float m = -1e30f;
#pragma unroll
    for (int k = 0; k < 10; ++k) {
        float s = fc2b[k];
#pragma unroll
        for (int j = 0; j < 32; ++j) s += z1[j] * fc2w[j * 10 + k];
        z2[k] = s;
        m = fmaxf(m, s);
    }
    float se = 0.f;
#pragma unroll
    for (int k = 0; k < 10; ++k) se += expf(z2[k] - m);
    float lse = m + logf(se);
#pragma unroll
    for (int k = 0; k < 10; ++k) out[g * 10 + k] = z2[k] - lse;
}

// ---------------------------------------------------------------------------
// Launch — kernel launches ONLY (graph-capturable, allocation-free)
// ---------------------------------------------------------------------------
extern "C" void kernel_launch(void* const* d_in, const int* in_sizes, int n_in,
                              void* d_out, int out_size) {
    const float* x     = (const float*)d_in[0];
    const int*   ei    = (const int*)d_in[1];    // int32
    const int*   batch = (const int*)d_in[2];    // int32
    const float* W1    = (const float*)d_in[3];
    const float* b1    = (const float*)d_in[4];
    const float* W2    = (const float*)d_in[5];
    const float* b2    = (const float*)d_in[6];
    const float* fc1w  = (const float*)d_in[7];
    const float* fc1b  = (const float*)d_in[8];
    const float* fc2w  = (const float*)d_in[9];
    const float* fc2b  = (const float*)d_in[10];
    float* out = (float*)d_out;

    int N = in_sizes[0] / 128;   // nodes
    int E = in_sizes[1] / 2;     // edges

    int gemm_blocks   = (N + 127) / 128;
    int edge_blocks   = (E + 255) / 256;
    int gather_blocks = (N * 32 + 255) / 256;

    // CSR build (reused by both layers) + zero accumulators
    zero_small_kernel<<<(N + 256) / 256, 256>>>(N);
    hist_kernel<<<edge_blocks, 256>>>(ei, E);
    scan_kernel<<<1, 1024>>>(N);
    fill_kernel<<<edge_blocks, 256>>>(ei, E);

    // Layer 1: g_h = x @ W1 ; g_agg = gather(g_h)
    gemm_nodes<128, false, false><<<gemm_blocks, 256>>>(x, W1, b1, N);
    gather_kernel<0><<<gather_blocks, 256>>>(b2, batch, N);

    // Layer 2: g_h = relu(g_agg + b1) @ W2 ; pool-fused gather
    gemm_nodes<64, true, true><<<gemm_blocks, 256>>>(x, W2, b1, N);
    gather_kernel<1><<<gather_blocks, 256>>>(b2, batch, N);

    // Head
    head_kernel<<<1, 64>>>(fc1w, fc1b, fc2w, fc2b, out);
}

// round 8
// speedup vs baseline: 1.2247x; 1.0210x over previous
#include <cuda_runtime.h>
#include <math.h>

#define N_NODES_MAX 50000
#define N_EDGES_MAX 800000
#define HDIM 64
#define N_GRAPHS 64

// Scratch (device globals — allocation-free, referenced directly in kernels)
__device__ __align__(16) float g_h[N_NODES_MAX * HDIM];     // 12.8 MB
__device__ __align__(16) float g_agg[N_NODES_MAX * HDIM];   // 12.8 MB
__device__ __align__(16) float g_gsum[N_GRAPHS * HDIM];
__device__ __align__(16) float g_gcnt[N_GRAPHS];
__device__ __align__(16) int g_deg[N_NODES_MAX + 4];
__device__ __align__(16) int g_rowptr[N_NODES_MAX + 4];
__device__ __align__(16) int g_cursor[N_NODES_MAX + 4];
__device__ __align__(16) int g_col[N_EDGES_MAX];

// ---------------------------------------------------------------------------
// Zero degree histogram + pool accumulators
// ---------------------------------------------------------------------------
__global__ void zero_small_kernel(int N) {
    int i = blockIdx.x * blockDim.x + threadIdx.x;
    if (i <= N)               g_deg[i]  = 0;
    if (i < N_GRAPHS * HDIM)  g_gsum[i] = 0.f;
    if (i < N_GRAPHS)         g_gcnt[i] = 0.f;
}

// ---------------------------------------------------------------------------
// CSR build: histogram (4 edges/thread), scan (4 elems/thread), fill (4/thread)
// ---------------------------------------------------------------------------
__global__ void hist_kernel(const int* __restrict__ ei, int E) {
    int e = (blockIdx.x * blockDim.x + threadIdx.x) * 4;
    if (e + 3 < E) {
        int4 d = *(const int4*)(ei + E + e);
        atomicAdd(&g_deg[d.x], 1);
        atomicAdd(&g_deg[d.y], 1);
        atomicAdd(&g_deg[d.z], 1);
        atomicAdd(&g_deg[d.w], 1);
    } else {
        for (int j = e; j < E; ++j) atomicAdd(&g_deg[__ldg(&ei[E + j])], 1);
    }
}

// Single-block exclusive scan of g_deg[0..N) -> g_rowptr / g_cursor
__global__ void scan_kernel(int N) {
    __shared__ int wsum[32];
    __shared__ int s_carry;
    int tid = threadIdx.x, lane = tid & 31, wid = tid >> 5;
    if (tid == 0) s_carry = 0;
    __syncthreads();
    const int CHUNK = 4096;   // 1024 threads * 4
    for (int base = 0; base < N; base += CHUNK) {
        int i0 = base + tid * 4;
        int v0 = 0, v1 = 0, v2 = 0, v3 = 0;
        if (i0 + 3 < N) {
            int4 v = *(const int4*)(g_deg + i0);
            v0 = v.x; v1 = v.y; v2 = v.z; v3 = v.w;
        } else {
            if (i0     < N) v0 = g_deg[i0];
            if (i0 + 1 < N) v1 = g_deg[i0 + 1];
            if (i0 + 2 < N) v2 = g_deg[i0 + 2];
            if (i0 + 3 < N) v3 = g_deg[i0 + 3];
        }
        int tsum = v0 + v1 + v2 + v3;
        int x = tsum;
#pragma unroll
        for (int o = 1; o < 32; o <<= 1) {
            int y = __shfl_up_sync(0xffffffffu, x, o);
            if (lane >= o) x += y;
        }
        if (lane == 31) wsum[wid] = x;
        __syncthreads();
        if (wid == 0) {
            int t = wsum[lane];
#pragma unroll
            for (int o = 1; o < 32; o <<= 1) {
                int y = __shfl_up_sync(0xffffffffu, t, o);
                if (lane >= o) t += y;
            }
            wsum[lane] = t;
        }
        __syncthreads();
        int excl = x - tsum + (wid > 0 ? wsum[wid - 1] : 0) + s_carry;
        int p0 = excl;
        int p1 = p0 + v0;
        int p2 = p1 + v1;
        int p3 = p2 + v2;
        if (i0     < N) { g_rowptr[i0]     = p0; g_cursor[i0]     = p0; }
        if (i0 + 1 < N) { g_rowptr[i0 + 1] = p1; g_cursor[i0 + 1] = p1; }
        if (i0 + 2 < N) { g_rowptr[i0 + 2] = p2; g_cursor[i0 + 2] = p2; }
        if (i0 + 3 < N) { g_rowptr[i0 + 3] = p3; g_cursor[i0 + 3] = p3; }
        int total = wsum[31];
        __syncthreads();
        if (tid == 0) s_carry += total;
        __syncthreads();
    }
    if (tid == 0) g_rowptr[N] = s_carry;
}

__global__ void fill_kernel(const int* __restrict__ ei, int E) {
    int e = (blockIdx.x * blockDim.x + threadIdx.x) * 4;
    if (e + 3 < E) {
        int4 s = *(const int4*)(ei + e);
        int4 d = *(const int4*)(ei + E + e);
        int p0 = atomicAdd(&g_cursor[d.x], 1);
        int p1 = atomicAdd(&g_cursor[d.y], 1);
        int p2 = atomicAdd(&g_cursor[d.z], 1);
        int p3 = atomicAdd(&g_cursor[d.w], 1);
        g_col[p0] = s.x;
        g_col[p1] = s.y;
        g_col[p2] = s.z;
        g_col[p3] = s.w;
    } else {
        for (int j = e; j < E; ++j) {
            int p = atomicAdd(&g_cursor[__ldg(&ei[E + j])], 1);
            g_col[p] = __ldg(&ei[j]);
        }
    }
}

// ---------------------------------------------------------------------------
// Atomic-free gather: one warp per node, each lane owns 2 feature columns.
//   MODE 0: g_agg[n] = relu( sum_{in-edges} g_h[src] + bias )   (layer output)
//   MODE 1: v = relu(sum + bias); red into g_gsum[batch[n]], count into g_gcnt
// ---------------------------------------------------------------------------
template <int MODE>
__global__ void gather_kernel(const float* __restrict__ bias,
                              const int* __restrict__ batch, int N) {
    int w = (blockIdx.x * blockDim.x + threadIdx.x) >> 5;
    if (w >= N) return;
    int lane = threadIdx.x & 31;
    int beg = __ldg(&g_rowptr[w]);
    int end = __ldg(&g_rowptr[w + 1]);

    const float2* hp = (const float2*)g_h;
    float2 acc = {0.f, 0.f};

    int i = beg;
    while (i < end) {
        int m = min(32, end - i);
        int c = (lane < m) ? __ldg(&g_col[i + lane]) : 0;
        int j = 0;
        for (; j + 8 <= m; j += 8) {
            int s0 = __shfl_sync(0xffffffffu, c, j);
            int s1 = __shfl_sync(0xffffffffu, c, j + 1);
            int s2 = __shfl_sync(0xffffffffu, c, j + 2);
            int s3 = __shfl_sync(0xffffffffu, c, j + 3);
            int s4 = __shfl_sync(0xffffffffu, c, j + 4);
            int s5 = __shfl_sync(0xffffffffu, c, j + 5);
            int s6 = __shfl_sync(0xffffffffu, c, j + 6);
            int s7 = __shfl_sync(0xffffffffu, c, j + 7);
            float2 v0 = hp[s0 * 32 + lane];
            float2 v1 = hp[s1 * 32 + lane];
            float2 v2 = hp[s2 * 32 + lane];
            float2 v3 = hp[s3 * 32 + lane];
            float2 v4 = hp[s4 * 32 + lane];
            float2 v5 = hp[s5 * 32 + lane];
            float2 v6 = hp[s6 * 32 + lane];
            float2 v7 = hp[s7 * 32 + lane];
            acc.x += ((v0.x + v1.x) + (v2.x + v3.x)) + ((v4.x + v5.x) + (v6.x + v7.x));
            acc.y += ((v0.y + v1.y) + (v2.y + v3.y)) + ((v4.y + v5.y) + (v6.y + v7.y));
        }
        for (; j < m; ++j) {
            int s = __shfl_sync(0xffffffffu, c, j);
            float2 v = hp[s * 32 + lane];
            acc.x += v.x;
            acc.y += v.y;
        }
        i += m;
    }

    float bx = __ldg(&bias[lane * 2]);
    float by = __ldg(&bias[lane * 2 + 1]);
    float vx = fmaxf(acc.x + bx, 0.f);
    float vy = fmaxf(acc.y + by, 0.f);

    if (MODE == 0) {
        float2 o = {vx, vy};
        ((float2*)g_agg)[w * 32 + lane] = o;
    } else {
        int g = __ldg(&batch[w]);
        atomicAdd(&g_gsum[g * HDIM + lane * 2],     vx);
        atomicAdd(&g_gsum[g * HDIM + lane * 2 + 1], vy);
        if (lane == 0) atomicAdd(&g_gcnt[g], 1.0f);
    }
}

// ---------------------------------------------------------------------------
// Register-tiled GEMM: g_h[n,64] = src(n,:K) @ W[K,64]
// Block = 256 threads, tile 128 rows x 64 cols; thread computes 8 rows x 4 cols.
// ---------------------------------------------------------------------------
template <int K, bool SRC_AGG>
__global__ void gemm_nodes(const float* __restrict__ X,
                           const float* __restrict__ Wg,
                           int N) {
    const int KC = 32;
    __shared__ float  xs[128][KC + 1];
    __shared__ float4 ws[KC][16];

    int tid = threadIdx.x;
    int cg  = tid & 15;
    int rt  = tid >> 4;
    int row0 = blockIdx.x * 128;

    float4 acc[8];
#pragma unroll
    for (int i = 0; i < 8; ++i) acc[i] = make_float4(0.f, 0.f, 0.f, 0.f);

    for (int kc = 0; kc < K; kc += KC) {
#pragma unroll
        for (int j = 0; j < 2; ++j) {
            int id = tid + 256 * j;
            int k = id >> 4, c = id & 15;
            ws[k][c] = ((const float4*)Wg)[(kc + k) * 16 + c];
        }
#pragma unroll
        for (int j = 0; j < 4; ++j) {
            int q = tid + 256 * j;
            int r = q >> 3, c4 = q & 7;
            int row = row0 + r;
            float4 v = make_float4(0.f, 0.f, 0.f, 0.f);
            if (row < N) {
                const float* srcp = SRC_AGG ? g_agg : X;
                v = *(const float4*)(srcp + row * K + kc + c4 * 4);
            }
            xs[r][c4 * 4]     = v.x;
            xs[r][c4 * 4 + 1] = v.y;
            xs[r][c4 * 4 + 2] = v.z;
            xs[r][c4 * 4 + 3] = v.w;
        }
        __syncthreads();

#pragma unroll
        for (int kk = 0; kk < KC; ++kk) {
            float4 w = ws[kk][cg];
#pragma unroll
            for (int i = 0; i < 8; ++i) {
                float xv = xs[rt * 8 + i][kk];
                acc[i].x += xv * w.x;
                acc[i].y += xv * w.y;
                acc[i].z += xv * w.z;
                acc[i].w += xv * w.w;
            }
        }
        __syncthreads();
    }

#pragma unroll
    for (int i = 0; i < 8; ++i) {
        int row = row0 + rt * 8 + i;
        if (row < N)
            ((float4*)&g_h[row * HDIM])[cg] = acc[i];
    }
}

// ---------------------------------------------------------------------------
// Head: pooled -> fc1(relu) -> fc2 -> log_softmax. One thread per graph.
// ---------------------------------------------------------------------------
__global__ void head_kernel(const float* __restrict__ fc1w,  // [64,32]
                            const float* __restrict__ fc1b,
                            const float* __restrict__ fc2w,  // [32,10]
                            const float* __restrict__ fc2b,
                            float* __restrict__ out) {
    int g = threadIdx.x;
    if (g >= N_GRAPHS) return;

    float inv = 1.0f / fmaxf(g_gcnt[g], 1.0f);
    float p[HDIM];
#pragma unroll
    for (int c = 0; c < HDIM; ++c) p[c] = g_gsum[g * HDIM + c] * inv;

    float z1[32];
#pragma unroll
    for (int j = 0; j < 32; ++j) {
        float s = fc1b[j];
#pragma unroll
        for (int c = 0; c < HDIM; ++c) s += p[c] * fc1w[c * 32 + j];
        z1[j] = fmaxf(s, 0.f);
    }

    float z2[10];
    float m = -1e30f;
#pragma unroll
    for (int k = 0; k < 10; ++k) {
        float s = fc2b[k];
#pragma unroll
        for (int j = 0; j < 32; ++j) s += z1[j] * fc2w[j * 10 + k];
        z2[k] = s;
        m = fmaxf(m, s);
    }
    float se = 0.f;
#pragma unroll
    for (int k = 0; k < 10; ++k) se += expf(z2[k] - m);
    float lse = m + logf(se);
#pragma unroll
    for (int k = 0; k < 10; ++k) out[g * 10 + k] = z2[k] - lse;
}

// ---------------------------------------------------------------------------
// Launch — kernel launches ONLY (graph-capturable, allocation-free)
// ---------------------------------------------------------------------------
extern "C" void kernel_launch(void* const* d_in, const int* in_sizes, int n_in,
                              void* d_out, int out_size) {
    const float* x     = (const float*)d_in[0];
    const int*   ei    = (const int*)d_in[1];    // int32
    const int*   batch = (const int*)d_in[2];    // int32
    const float* W1    = (const float*)d_in[3];
    const float* b1    = (const float*)d_in[4];
    const float* W2    = (const float*)d_in[5];
    const float* b2    = (const float*)d_in[6];
    const float* fc1w  = (const float*)d_in[7];
    const float* fc1b  = (const float*)d_in[8];
    const float* fc2w  = (const float*)d_in[9];
    const float* fc2b  = (const float*)d_in[10];
    float* out = (float*)d_out;

    int N = in_sizes[0] / 128;   // nodes
    int E = in_sizes[1] / 2;     // edges

    int gemm_blocks   = (N + 127) / 128;
    int edge4_blocks  = (E / 4 + 255) / 256 + 1;
    int gather_blocks = (N * 32 + 255) / 256;

    // CSR build (reused by both layers) + zero accumulators
    zero_small_kernel<<<(N + 256) / 256, 256>>>(N);
    hist_kernel<<<edge4_blocks, 256>>>(ei, E);
    scan_kernel<<<1, 1024>>>(N);
    fill_kernel<<<edge4_blocks, 256>>>(ei, E);

    // Layer 1: g_h = x @ W1 ; g_agg = relu(gather(g_h) + b1)
    gemm_nodes<128, false><<<gemm_blocks, 256>>>(x, W1, N);
    gather_kernel<0><<<gather_blocks, 256>>>(b1, batch, N);

    // Layer 2: g_h = g_agg @ W2 ; pool-fused gather with b2
    gemm_nodes<64, true><<<gemm_blocks, 256>>>(x, W2, N);
    gather_kernel<1><<<gather_blocks, 256>>>(b2, batch, N);

    // Head
    head_kernel<<<1, 64>>>(fc1w, fc1b, fc2w, fc2b, out);
}

// round 9
// speedup vs baseline: 1.2675x; 1.0349x over previous
#include <cuda_runtime.h>
#include <math.h>

#define N_NODES_MAX 50000
#define N_EDGES_MAX 800000
#define HDIM 64
#define N_GRAPHS 64

// Scratch (device globals — allocation-free, referenced directly in kernels)
__device__ __align__(16) float g_h[N_NODES_MAX * HDIM];     // 12.8 MB
__device__ __align__(16) float g_agg[N_NODES_MAX * HDIM];   // 12.8 MB
__device__ __align__(16) float g_gsum[N_GRAPHS * HDIM];
__device__ __align__(16) float g_gcnt[N_GRAPHS];
__device__ __align__(16) int g_deg[N_NODES_MAX + 4];
__device__ __align__(16) int g_rowptr[N_NODES_MAX + 4];
__device__ __align__(16) int g_cursor[N_NODES_MAX + 4];
__device__ __align__(16) int g_col[N_EDGES_MAX];

// ---------------------------------------------------------------------------
// Zero degree histogram + pool accumulators
// ---------------------------------------------------------------------------
__global__ void zero_small_kernel(int N) {
    int i = blockIdx.x * blockDim.x + threadIdx.x;
    if (i <= N)               g_deg[i]  = 0;
    if (i < N_GRAPHS * HDIM)  g_gsum[i] = 0.f;
    if (i < N_GRAPHS)         g_gcnt[i] = 0.f;
}

// ---------------------------------------------------------------------------
// CSR build: histogram, single-block scan, fill
// ---------------------------------------------------------------------------
__global__ void hist_kernel(const int* __restrict__ ei, int E) {
    int e = (blockIdx.x * blockDim.x + threadIdx.x) * 4;
    if (e + 3 < E) {
        int4 d = *(const int4*)(ei + E + e);
        atomicAdd(&g_deg[d.x], 1);
        atomicAdd(&g_deg[d.y], 1);
        atomicAdd(&g_deg[d.z], 1);
        atomicAdd(&g_deg[d.w], 1);
    } else {
        for (int j = e; j < E; ++j) atomicAdd(&g_deg[__ldg(&ei[E + j])], 1);
    }
}

__global__ void scan_kernel(int N) {
    __shared__ int wsum[32];
    __shared__ int s_carry;
    int tid = threadIdx.x, lane = tid & 31, wid = tid >> 5;
    if (tid == 0) s_carry = 0;
    __syncthreads();
    const int CHUNK = 4096;   // 1024 threads * 4
    for (int base = 0; base < N; base += CHUNK) {
        int i0 = base + tid * 4;
        int v0 = 0, v1 = 0, v2 = 0, v3 = 0;
        if (i0 + 3 < N) {
            int4 v = *(const int4*)(g_deg + i0);
            v0 = v.x; v1 = v.y; v2 = v.z; v3 = v.w;
        } else {
            if (i0     < N) v0 = g_deg[i0];
            if (i0 + 1 < N) v1 = g_deg[i0 + 1];
            if (i0 + 2 < N) v2 = g_deg[i0 + 2];
            if (i0 + 3 < N) v3 = g_deg[i0 + 3];
        }
        int tsum = v0 + v1 + v2 + v3;
        int x = tsum;
#pragma unroll
        for (int o = 1; o < 32; o <<= 1) {
            int y = __shfl_up_sync(0xffffffffu, x, o);
            if (lane >= o) x += y;
        }
        if (lane == 31) wsum[wid] = x;
        __syncthreads();
        if (wid == 0) {
            int t = wsum[lane];
#pragma unroll
            for (int o = 1; o < 32; o <<= 1) {
                int y = __shfl_up_sync(0xffffffffu, t, o);
                if (lane >= o) t += y;
            }
            wsum[lane] = t;
        }
        __syncthreads();
        int excl = x - tsum + (wid > 0 ? wsum[wid - 1] : 0) + s_carry;
        int p0 = excl;
        int p1 = p0 + v0;
        int p2 = p1 + v1;
        int p3 = p2 + v2;
        if (i0     < N) { g_rowptr[i0]     = p0; g_cursor[i0]     = p0; }
        if (i0 + 1 < N) { g_rowptr[i0 + 1] = p1; g_cursor[i0 + 1] = p1; }
        if (i0 + 2 < N) { g_rowptr[i0 + 2] = p2; g_cursor[i0 + 2] = p2; }
        if (i0 + 3 < N) { g_rowptr[i0 + 3] = p3; g_cursor[i0 + 3] = p3; }
        int total = wsum[31];
        __syncthreads();
        if (tid == 0) s_carry += total;
        __syncthreads();
    }
    if (tid == 0) g_rowptr[N] = s_carry;
}

__global__ void fill_kernel(const int* __restrict__ ei, int E) {
    int e = (blockIdx.x * blockDim.x + threadIdx.x) * 4;
    if (e + 3 < E) {
        int4 s = *(const int4*)(ei + e);
        int4 d = *(const int4*)(ei + E + e);
        int p0 = atomicAdd(&g_cursor[d.x], 1);
        int p1 = atomicAdd(&g_cursor[d.y], 1);
        int p2 = atomicAdd(&g_cursor[d.z], 1);
        int p3 = atomicAdd(&g_cursor[d.w], 1);
        g_col[p0] = s.x;
        g_col[p1] = s.y;
        g_col[p2] = s.z;
        g_col[p3] = s.w;
    } else {
        for (int j = e; j < E; ++j) {
            int p = atomicAdd(&g_cursor[__ldg(&ei[E + j])], 1);
            g_col[p] = __ldg(&ei[j]);
        }
    }
}

// ---------------------------------------------------------------------------
// Atomic-free gather: one warp per node, each lane owns 2 feature columns.
//   MODE 0: g_agg[n] = relu( sum_{in-edges} g_h[src] + bias )
//   MODE 1: v = relu(sum + bias); red into g_gsum[batch[n]], count into g_gcnt
// ---------------------------------------------------------------------------
template <int MODE>
__global__ void __launch_bounds__(256, 8)
gather_kernel(const float* __restrict__ bias,
              const int* __restrict__ batch, int N) {
    int w = (blockIdx.x * blockDim.x + threadIdx.x) >> 5;
    if (w >= N) return;
    int lane = threadIdx.x & 31;
    int beg = __ldg(&g_rowptr[w]);
    int end = __ldg(&g_rowptr[w + 1]);

    const float2* hp = (const float2*)g_h;
    float2 acc = {0.f, 0.f};

    int i = beg;
    while (i < end) {
        int m = min(32, end - i);
        int c = (lane < m) ? __ldg(&g_col[i + lane]) : 0;
        int j = 0;
        for (; j + 8 <= m; j += 8) {
            int s0 = __shfl_sync(0xffffffffu, c, j);
            int s1 = __shfl_sync(0xffffffffu, c, j + 1);
            int s2 = __shfl_sync(0xffffffffu, c, j + 2);
            int s3 = __shfl_sync(0xffffffffu, c, j + 3);
            int s4 = __shfl_sync(0xffffffffu, c, j + 4);
            int s5 = __shfl_sync(0xffffffffu, c, j + 5);
            int s6 = __shfl_sync(0xffffffffu, c, j + 6);
            int s7 = __shfl_sync(0xffffffffu, c, j + 7);
            float2 v0 = hp[s0 * 32 + lane];
            float2 v1 = hp[s1 * 32 + lane];
            float2 v2 = hp[s2 * 32 + lane];
            float2 v3 = hp[s3 * 32 + lane];
            float2 v4 = hp[s4 * 32 + lane];
            float2 v5 = hp[s5 * 32 + lane];
            float2 v6 = hp[s6 * 32 + lane];
            float2 v7 = hp[s7 * 32 + lane];
            acc.x += ((v0.x + v1.x) + (v2.x + v3.x)) + ((v4.x + v5.x) + (v6.x + v7.x));
            acc.y += ((v0.y + v1.y) + (v2.y + v3.y)) + ((v4.y + v5.y) + (v6.y + v7.y));
        }
        for (; j < m; ++j) {
            int s = __shfl_sync(0xffffffffu, c, j);
            float2 v = hp[s * 32 + lane];
            acc.x += v.x;
            acc.y += v.y;
        }
        i += m;
    }

    float bx = __ldg(&bias[lane * 2]);
    float by = __ldg(&bias[lane * 2 + 1]);
    float vx = fmaxf(acc.x + bx, 0.f);
    float vy = fmaxf(acc.y + by, 0.f);

    if (MODE == 0) {
        float2 o = {vx, vy};
        ((float2*)g_agg)[w * 32 + lane] = o;
    } else {
        int g = __ldg(&batch[w]);
        atomicAdd(&g_gsum[g * HDIM + lane * 2],     vx);
        atomicAdd(&g_gsum[g * HDIM + lane * 2 + 1], vy);
        if (lane == 0) atomicAdd(&g_gcnt[g], 1.0f);
    }
}

// ---------------------------------------------------------------------------
// Register-tiled GEMM: g_h[n,64] = src(n,:K) @ W[K,64]
// ---------------------------------------------------------------------------
template <int K, bool SRC_AGG>
__global__ void gemm_nodes(const float* __restrict__ X,
                           const float* __restrict__ Wg,
                           int N) {
    const int KC = 32;
    __shared__ float  xs[128][KC + 1];
    __shared__ float4 ws[KC][16];

    int tid = threadIdx.x;
    int cg  = tid & 15;
    int rt  = tid >> 4;
    int row0 = blockIdx.x * 128;

    float4 acc[8];
#pragma unroll
    for (int i = 0; i < 8; ++i) acc[i] = make_float4(0.f, 0.f, 0.f, 0.f);

    for (int kc = 0; kc < K; kc += KC) {
#pragma unroll
        for (int j = 0; j < 2; ++j) {
            int id = tid + 256 * j;
            int k = id >> 4, c = id & 15;
            ws[k][c] = ((const float4*)Wg)[(kc + k) * 16 + c];
        }
#pragma unroll
        for (int j = 0; j < 4; ++j) {
            int q = tid + 256 * j;
            int r = q >> 3, c4 = q & 7;
            int row = row0 + r;
            float4 v = make_float4(0.f, 0.f, 0.f, 0.f);
            if (row < N) {
                const float* srcp = SRC_AGG ? g_agg : X;
                v = *(const float4*)(srcp + row * K + kc + c4 * 4);
            }
            xs[r][c4 * 4]     = v.x;
            xs[r][c4 * 4 + 1] = v.y;
            xs[r][c4 * 4 + 2] = v.z;
            xs[r][c4 * 4 + 3] = v.w;
        }
        __syncthreads();

#pragma unroll
        for (int kk = 0; kk < KC; ++kk) {
            float4 w = ws[kk][cg];
#pragma unroll
            for (int i = 0; i < 8; ++i) {
                float xv = xs[rt * 8 + i][kk];
                acc[i].x += xv * w.x;
                acc[i].y += xv * w.y;
                acc[i].z += xv * w.z;
                acc[i].w += xv * w.w;
            }
        }
        __syncthreads();
    }

#pragma unroll
    for (int i = 0; i < 8; ++i) {
        int row = row0 + rt * 8 + i;
        if (row < N)
            ((float4*)&g_h[row * HDIM])[cg] = acc[i];
    }
}

// ---------------------------------------------------------------------------
// Head: pooled -> fc1(relu) -> fc2 -> log_softmax. One thread per graph.
// ---------------------------------------------------------------------------
__global__ void head_kernel(const float* __restrict__ fc1w,  // [64,32]
                            const float* __restrict__ fc1b,
                            const float* __restrict__ fc2w,  // [32,10]
                            const float* __restrict__ fc2b,
                            float* __restrict__ out) {
    int g = threadIdx.x;
    if (g >= N_GRAPHS) return;

    float inv = 1.0f / fmaxf(g_gcnt[g], 1.0f);
    float p[HDIM];
#pragma unroll
    for (int c = 0; c < HDIM; ++c) p[c] = g_gsum[g * HDIM + c] * inv;

    float z1[32];
#pragma unroll
    for (int j = 0; j < 32; ++j) {
        float s = fc1b[j];
#pragma unroll
        for (int c = 0; c < HDIM; ++c) s += p[c] * fc1w[c * 32 + j];
        z1[j] = fmaxf(s, 0.f);
    }

    float z2[10];
    float m = -1e30f;
#pragma unroll
    for (int k = 0; k < 10; ++k) {
        float s = fc2b[k];
#pragma unroll
        for (int j = 0; j < 32; ++j) s += z1[j] * fc2w[j * 10 + k];
        z2[k] = s;
        m = fmaxf(m, s);
    }
    float se = 0.f;
#pragma unroll
    for (int k = 0; k < 10; ++k) se += expf(z2[k] - m);
    float lse = m + logf(se);
#pragma unroll
    for (int k = 0; k < 10; ++k) out[g * 10 + k] = z2[k] - lse;
}

// ---------------------------------------------------------------------------
// Launch — capturable ops only (launches + event fork/join). Streams/events
// are lazily created OUTSIDE capture (first call is the uncaptured
// correctness run); per-call work is identical every call.
// ---------------------------------------------------------------------------
static cudaStream_t s_side = 0;
static cudaEvent_t  s_ev_fork = 0, s_ev_join = 0;

extern "C" void kernel_launch(void* const* d_in, const int* in_sizes, int n_in,
                              void* d_out, int out_size) {
    const float* x     = (const float*)d_in[0];
    const int*   ei    = (const int*)d_in[1];    // int32
    const int*   batch = (const int*)d_in[2];    // int32
    const float* W1    = (const float*)d_in[3];
    const float* b1    = (const float*)d_in[4];
    const float* W2    = (const float*)d_in[5];
    const float* b2    = (const float*)d_in[6];
    const float* fc1w  = (const float*)d_in[7];
    const float* fc1b  = (const float*)d_in[8];
    const float* fc2w  = (const float*)d_in[9];
    const float* fc2b  = (const float*)d_in[10];
    float* out = (float*)d_out;

    int N = in_sizes[0] / 128;   // nodes
    int E = in_sizes[1] / 2;     // edges

    if (!s_side) {
        cudaStreamCreateWithFlags(&s_side, cudaStreamNonBlocking);
        cudaEventCreateWithFlags(&s_ev_fork, cudaEventDisableTiming);
        cudaEventCreateWithFlags(&s_ev_join, cudaEventDisableTiming);
    }

    int gemm_blocks   = (N + 127) / 128;
    int edge4_blocks  = (E / 4 + 255) / 256 + 1;
    int gather_blocks = (N * 32 + 255) / 256;

    // Fork: CSR build on side stream, concurrent with gemm1 on main stream
    cudaEventRecord(s_ev_fork, 0);
    cudaStreamWaitEvent(s_side, s_ev_fork, 0);

    zero_small_kernel<<<(N + 256) / 256, 256, 0, s_side>>>(N);
    hist_kernel<<<edge4_blocks, 256, 0, s_side>>>(ei, E);
    scan_kernel<<<1, 1024, 0, s_side>>>(N);
    fill_kernel<<<edge4_blocks, 256, 0, s_side>>>(ei, E);
    cudaEventRecord(s_ev_join, s_side);

    // Main stream: gemm1 overlaps the build
    gemm_nodes<128, false><<<gemm_blocks, 256>>>(x, W1, N);

    // Join: gather needs both g_h and the CSR
    cudaStreamWaitEvent(0, s_ev_join, 0);

    // Layer 1 aggregate: g_agg = relu(gather(g_h) + b1)
    gather_kernel<0><<<gather_blocks, 256>>>(b1, batch, N);

    // Layer 2: g_h = g_agg @ W2 ; pool-fused gather with b2
    gemm_nodes<64, true><<<gemm_blocks, 256>>>(x, W2, N);
    gather_kernel<1><<<gather_blocks, 256>>>(b2, batch, N);

    // Head
    head_kernel<<<1, 64>>>(fc1w, fc1b, fc2w, fc2b, out);
}

// round 10
// speedup vs baseline: 1.4597x; 1.1516x over previous
#include <cuda_runtime.h>
#include <math.h>

#define N_NODES_MAX 50000
#define N_EDGES_MAX 800000
#define HDIM 64
#define N_GRAPHS 64

// Scratch (device globals — allocation-free, referenced directly in kernels)
__device__ __align__(16) float g_h[N_NODES_MAX * HDIM];     // 12.8 MB
__device__ __align__(16) float g_agg[N_NODES_MAX * HDIM];   // 12.8 MB
__device__ __align__(16) float g_gsum[N_GRAPHS * HDIM];
__device__ __align__(16) float g_gcnt[N_GRAPHS];
__device__ __align__(16) int g_deg[N_NODES_MAX + 4];
__device__ __align__(16) int g_rowptr[N_NODES_MAX + 4];
__device__ __align__(16) int g_rank[N_EDGES_MAX + 4];
__device__ __align__(16) int g_col[N_EDGES_MAX];

// ---------------------------------------------------------------------------
// Zero degree histogram + pool accumulators
// ---------------------------------------------------------------------------
__global__ void zero_small_kernel(int N) {
    int i = blockIdx.x * blockDim.x + threadIdx.x;
    if (i <= N)               g_deg[i]  = 0;
    if (i < N_GRAPHS * HDIM)  g_gsum[i] = 0.f;
    if (i < N_GRAPHS)         g_gcnt[i] = 0.f;
}

// ---------------------------------------------------------------------------
// CSR build.
// hist: degree histogram; the atomic's RETURN VALUE is the edge's rank within
//       its dst bucket (stored to g_rank) -> fill needs no atomics at all.
// ---------------------------------------------------------------------------
__global__ void hist_kernel(const int* __restrict__ ei, int E) {
    int e = (blockIdx.x * blockDim.x + threadIdx.x) * 4;
    if (e + 3 < E) {
        int4 d = *(const int4*)(ei + E + e);
        int4 r;
        r.x = atomicAdd(&g_deg[d.x], 1);
        r.y = atomicAdd(&g_deg[d.y], 1);
        r.z = atomicAdd(&g_deg[d.z], 1);
        r.w = atomicAdd(&g_deg[d.w], 1);
        *(int4*)(g_rank + e) = r;
    } else {
        for (int j = e; j < E; ++j)
            g_rank[j] = atomicAdd(&g_deg[__ldg(&ei[E + j])], 1);
    }
}

// Single-block exclusive scan of g_deg[0..N) -> g_rowptr
__global__ void scan_kernel(int N) {
    __shared__ int wsum[32];
    __shared__ int s_carry;
    int tid = threadIdx.x, lane = tid & 31, wid = tid >> 5;
    if (tid == 0) s_carry = 0;
    __syncthreads();
    const int CHUNK = 4096;   // 1024 threads * 4
    for (int base = 0; base < N; base += CHUNK) {
        int i0 = base + tid * 4;
        int v0 = 0, v1 = 0, v2 = 0, v3 = 0;
        if (i0 + 3 < N) {
            int4 v = *(const int4*)(g_deg + i0);
            v0 = v.x; v1 = v.y; v2 = v.z; v3 = v.w;
        } else {
            if (i0     < N) v0 = g_deg[i0];
            if (i0 + 1 < N) v1 = g_deg[i0 + 1];
            if (i0 + 2 < N) v2 = g_deg[i0 + 2];
            if (i0 + 3 < N) v3 = g_deg[i0 + 3];
        }
        int tsum = v0 + v1 + v2 + v3;
        int x = tsum;
#pragma unroll
        for (int o = 1; o < 32; o <<= 1) {
            int y = __shfl_up_sync(0xffffffffu, x, o);
            if (lane >= o) x += y;
        }
        if (lane == 31) wsum[wid] = x;
        __syncthreads();
        if (wid == 0) {
            int t = wsum[lane];
#pragma unroll
            for (int o = 1; o < 32; o <<= 1) {
                int y = __shfl_up_sync(0xffffffffu, t, o);
                if (lane >= o) t += y;
            }
            wsum[lane] = t;
        }
        __syncthreads();
        int excl = x - tsum + (wid > 0 ? wsum[wid - 1] : 0) + s_carry;
        if (i0     < N) g_rowptr[i0]     = excl;
        if (i0 + 1 < N) g_rowptr[i0 + 1] = excl + v0;
        if (i0 + 2 < N) g_rowptr[i0 + 2] = excl + v0 + v1;
        if (i0 + 3 < N) g_rowptr[i0 + 3] = excl + v0 + v1 + v2;
        int total = wsum[31];
        __syncthreads();
        if (tid == 0) s_carry += total;
        __syncthreads();
    }
    if (tid == 0) g_rowptr[N] = s_carry;
}

// Atomic-free fill: g_col[rowptr[dst] + rank[e]] = src
__global__ void fill_kernel(const int* __restrict__ ei, int E) {
    int e = (blockIdx.x * blockDim.x + threadIdx.x) * 4;
    if (e + 3 < E) {
        int4 s = *(const int4*)(ei + e);
        int4 d = *(const int4*)(ei + E + e);
        int4 r = *(const int4*)(g_rank + e);
        int p0 = __ldg(&g_rowptr[d.x]) + r.x;
        int p1 = __ldg(&g_rowptr[d.y]) + r.y;
        int p2 = __ldg(&g_rowptr[d.z]) + r.z;
        int p3 = __ldg(&g_rowptr[d.w]) + r.w;
        g_col[p0] = s.x;
        g_col[p1] = s.y;
        g_col[p2] = s.z;
        g_col[p3] = s.w;
    } else {
        for (int j = e; j < E; ++j)
            g_col[__ldg(&g_rowptr[__ldg(&ei[E + j])]) + g_rank[j]] = __ldg(&ei[j]);
    }
}

// ---------------------------------------------------------------------------
// Atomic-free gather: one warp per node; half-warp per edge, float4 per lane
// (2 edges per warp-instruction, 4 LDG.128 in flight).
//   MODE 0: g_agg[n] = relu( sum_{in-edges} g_h[src] + bias )
//   MODE 1: v = relu(sum + bias); float4 red into g_gsum[batch[n]]
// ---------------------------------------------------------------------------
template <int MODE>
__global__ void __launch_bounds__(256, 8)
gather_kernel(const float* __restrict__ bias,
              const int* __restrict__ batch, int N) {
    int w = (blockIdx.x * blockDim.x + threadIdx.x) >> 5;
    if (w >= N) return;
    int lane = threadIdx.x & 31;
    int half = lane >> 4;     // which edge of the pair
    int hl   = lane & 15;     // float4 slot within the 64-float row
    int beg = __ldg(&g_rowptr[w]);
    int end = __ldg(&g_rowptr[w + 1]);

    const float4* hp = (const float4*)g_h;   // 16 float4 per row
    float4 acc = {0.f, 0.f, 0.f, 0.f};

    int i = beg;
    while (i < end) {
        int m = min(32, end - i);
        int c = (lane < m) ? __ldg(&g_col[i + lane]) : 0;
        int j = 0;
        for (; j + 8 <= m; j += 8) {     // 8 edges = 4 pair-steps in flight
            int s0 = __shfl_sync(0xffffffffu, c, j     + half);
            int s1 = __shfl_sync(0xffffffffu, c, j + 2 + half);
            int s2 = __shfl_sync(0xffffffffu, c, j + 4 + half);
            int s3 = __shfl_sync(0xffffffffu, c, j + 6 + half);
            float4 v0 = hp[s0 * 16 + hl];
            float4 v1 = hp[s1 * 16 + hl];
            float4 v2 = hp[s2 * 16 + hl];
            float4 v3 = hp[s3 * 16 + hl];
            acc.x += (v0.x + v1.x) + (v2.x + v3.x);
            acc.y += (v0.y + v1.y) + (v2.y + v3.y);
            acc.z += (v0.z + v1.z) + (v2.z + v3.z);
            acc.w += (v0.w + v1.w) + (v2.w + v3.w);
        }
        for (; j < m; j += 2) {          // tail pairs
            int idx = j + half;
            bool valid = idx < m;
            int s = __shfl_sync(0xffffffffu, c, valid ? idx : m - 1);
            float4 v = hp[s * 16 + hl];
            if (valid) {
                acc.x += v.x; acc.y += v.y; acc.z += v.z; acc.w += v.w;
            }
        }
        i += m;
    }

    // Combine the two half-warp partial sums
    acc.x += __shfl_xor_sync(0xffffffffu, acc.x, 16);
    acc.y += __shfl_xor_sync(0xffffffffu, acc.y, 16);
    acc.z += __shfl_xor_sync(0xffffffffu, acc.z, 16);
    acc.w += __shfl_xor_sync(0xffffffffu, acc.w, 16);

    if (half == 0) {
        float4 b = ((const float4*)bias)[hl];
        float4 o;
        o.x = fmaxf(acc.x + b.x, 0.f);
        o.y = fmaxf(acc.y + b.y, 0.f);
        o.z = fmaxf(acc.z + b.z, 0.f);
        o.w = fmaxf(acc.w + b.w, 0.f);
        if (MODE == 0) {
            ((float4*)g_agg)[w * 16 + hl] = o;
        } else {
            int g = __ldg(&batch[w]);
            atomicAdd((float4*)(g_gsum + g * HDIM + hl * 4), o);
            if (hl == 0) atomicAdd(&g_gcnt[g], 1.0f);
        }
    }
}

// ---------------------------------------------------------------------------
// Register-tiled GEMM: g_h[n,64] = src(n,:K) @ W[K,64]
// ---------------------------------------------------------------------------
template <int K, bool SRC_AGG>
__global__ void gemm_nodes(const float* __restrict__ X,
                           const float* __restrict__ Wg,
                           int N) {
    const int KC = 32;
    __shared__ float  xs[128][KC + 1];
    __shared__ float4 ws[KC][16];

    int tid = threadIdx.x;
    int cg  = tid & 15;
    int rt  = tid >> 4;
    int row0 = blockIdx.x * 128;

    float4 acc[8];
#pragma unroll
    for (int i = 0; i < 8; ++i) acc[i] = make_float4(0.f, 0.f, 0.f, 0.f);

    for (int kc = 0; kc < K; kc += KC) {
#pragma unroll
        for (int j = 0; j < 2; ++j) {
            int id = tid + 256 * j;
            int k = id >> 4, c = id & 15;
            ws[k][c] = ((const float4*)Wg)[(kc + k) * 16 + c];
        }
#pragma unroll
        for (int j = 0; j < 4; ++j) {
            int q = tid + 256 * j;
            int r = q >> 3, c4 = q & 7;
            int row = row0 + r;
            float4 v = make_float4(0.f, 0.f, 0.f, 0.f);
            if (row < N) {
                const float* srcp = SRC_AGG ? g_agg : X;
                v = *(const float4*)(srcp + row * K + kc + c4 * 4);
            }
            xs[r][c4 * 4]     = v.x;
            xs[r][c4 * 4 + 1] = v.y;
            xs[r][c4 * 4 + 2] = v.z;
            xs[r][c4 * 4 + 3] = v.w;
        }
        __syncthreads();

#pragma unroll
        for (int kk = 0; kk < KC; ++kk) {
            float4 w = ws[kk][cg];
#pragma unroll
            for (int i = 0; i < 8; ++i) {
                float xv = xs[rt * 8 + i][kk];
                acc[i].x += xv * w.x;
                acc[i].y += xv * w.y;
                acc[i].z += xv * w.z;
                acc[i].w += xv * w.w;
            }
        }
        __syncthreads();
    }

#pragma unroll
    for (int i = 0; i < 8; ++i) {
        int row = row0 + rt * 8 + i;
        if (row < N)
            ((float4*)&g_h[row * HDIM])[cg] = acc[i];
    }
}

// ---------------------------------------------------------------------------
// Head: pooled -> fc1(relu) -> fc2 -> log_softmax. One thread per graph.
// ---------------------------------------------------------------------------
__global__ void head_kernel(const float* __restrict__ fc1w,  // [64,32]
                            const float* __restrict__ fc1b,
                            const float* __restrict__ fc2w,  // [32,10]
                            const float* __restrict__ fc2b,
                            float* __restrict__ out) {
    int g = threadIdx.x;
    if (g >= N_GRAPHS) return;

    float inv = 1.0f / fmaxf(g_gcnt[g], 1.0f);
    float p[HDIM];
#pragma unroll
    for (int c = 0; c < HDIM; ++c) p[c] = g_gsum[g * HDIM + c] * inv;

    float z1[32];
#pragma unroll
    for (int j = 0; j < 32; ++j) {
        float s = fc1b[j];
#pragma unroll
        for (int c = 0; c < HDIM; ++c) s += p[c] * fc1w[c * 32 + j];
        z1[j] = fmaxf(s, 0.f);
    }

    float z2[10];
    float m = -1e30f;
#pragma unroll
    for (int k = 0; k < 10; ++k) {
        float s = fc2b[k];
#pragma unroll
        for (int j = 0; j < 32; ++j) s += z1[j] * fc2w[j * 10 + k];
        z2[k] = s;
        m = fmaxf(m, s);
    }
    float se = 0.f;
#pragma unroll
    for (int k = 0; k < 10; ++k) se += expf(z2[k] - m);
    float lse = m + logf(se);
#pragma unroll
    for (int k = 0; k < 10; ++k) out[g * 10 + k] = z2[k] - lse;
}

// ---------------------------------------------------------------------------
// Launch — capturable ops only (launches + event fork/join). Streams/events
// lazily created OUTSIDE capture (first call is the uncaptured correctness
// run); per-call work identical every call.
// ---------------------------------------------------------------------------
static cudaStream_t s_side = 0;
static cudaEvent_t  s_ev_fork = 0, s_ev_join = 0;

extern "C" void kernel_launch(void* const* d_in, const int* in_sizes, int n_in,
                              void* d_out, int out_size) {
    const float* x     = (const float*)d_in[0];
    const int*   ei    = (const int*)d_in[1];    // int32
    const int*   batch = (const int*)d_in[2];    // int32
    const float* W1    = (const float*)d_in[3];
    const float* b1    = (const float*)d_in[4];
    const float* W2    = (const float*)d_in[5];
    const float* b2    = (const float*)d_in[6];
    const float* fc1w  = (const float*)d_in[7];
    const float* fc1b  = (const float*)d_in[8];
    const float* fc2w  = (const float*)d_in[9];
    const float* fc2b  = (const float*)d_in[10];
    float* out = (float*)d_out;

    int N = in_sizes[0] / 128;   // nodes
    int E = in_sizes[1] / 2;     // edges

    if (!s_side) {
        cudaStreamCreateWithFlags(&s_side, cudaStreamNonBlocking);
        cudaEventCreateWithFlags(&s_ev_fork, cudaEventDisableTiming);
        cudaEventCreateWithFlags(&s_ev_join, cudaEventDisableTiming);
    }

    int gemm_blocks   = (N + 127) / 128;
    int edge4_blocks  = (E / 4 + 255) / 256 + 1;
    int gather_blocks = (N * 32 + 255) / 256;

    // Fork: CSR build on side stream, concurrent with gemm1 on main stream
    cudaEventRecord(s_ev_fork, 0);
    cudaStreamWaitEvent(s_side, s_ev_fork, 0);

    zero_small_kernel<<<(N + 256) / 256, 256, 0, s_side>>>(N);
    hist_kernel<<<edge4_blocks, 256, 0, s_side>>>(ei, E);
    scan_kernel<<<1, 1024, 0, s_side>>>(N);
    fill_kernel<<<edge4_blocks, 256, 0, s_side>>>(ei, E);
    cudaEventRecord(s_ev_join, s_side);

    // Main stream: gemm1 overlaps the build
    gemm_nodes<128, false><<<gemm_blocks, 256>>>(x, W1, N);

    // Join: gather needs both g_h and the CSR
    cudaStreamWaitEvent(0, s_ev_join, 0);

    // Layer 1 aggregate: g_agg = relu(gather(g_h) + b1)
    gather_kernel<0><<<gather_blocks, 256>>>(b1, batch, N);

    // Layer 2: g_h = g_agg @ W2 ; pool-fused gather with b2
    gemm_nodes<64, true><<<gemm_blocks, 256>>>(x, W2, N);
    gather_kernel<1><<<gather_blocks, 256>>>(b2, batch, N);

    // Head
    head_kernel<<<1, 64>>>(fc1w, fc1b, fc2w, fc2b, out);
}